// round 17
// baseline (speedup 1.0000x reference)
#include <cuda_runtime.h>
#include <cuda_fp16.h>
#include <cuda_pipeline.h>
#include <cstdint>
#include <math.h>

#define Bb 128
#define Rr 1152
#define CI 8
#define Cc 10
#define Oo 16
#define NS  (Cc*Bb*Oo)   /* 20480 */
#define RT 16
#define NRT (Rr/RT)      /* 72 */
#define DEPTH 9
#define CHB 2048         /* chunk bytes: 128 thr * 16B */
#define NCHUNK 9         /* half tile: 18432 / 2048 */
#define NIT_CTAS (Bb*2*Cc)  /* 2560 */

// Static device scratch.
__device__ __half g_uh[(size_t)Cc*Bb*Rr*Oo];  // 47 MB, u in fp16
__device__ float  g_S[NS];                    // current s[c][b][o]
__device__ float  g_V[NS];                    // accumulated V (pre-scaled log2e)
__device__ float  g_zp[NS*2];                 // per-half partial z
__device__ float  g_sp[NS*2];                 // per-half partial s
__device__ float  g_n2a[640];                 // per-CTA sum-sq partials (k_s0)
__device__ float  g_n2s[2];                   // scalar n2 after s1 / after iter2
__device__ int    g_ctr[3];                   // last-CTA counters (reset by k_u)

// ---------------------------------------------------------------------------
// f32x2 packed helpers
// ---------------------------------------------------------------------------
typedef unsigned long long ull;
__device__ __forceinline__ ull pk2(float lo, float hi) {
    ull r; asm("mov.b64 %0, {%1, %2};" : "=l"(r) : "f"(lo), "f"(hi)); return r;
}
__device__ __forceinline__ void upk2(ull v, float& lo, float& hi) {
    asm("mov.b64 {%0, %1}, %2;" : "=f"(lo), "=f"(hi) : "l"(v));
}
__device__ __forceinline__ ull fma2(ull a, ull b, ull c) {
    ull r; asm("fma.rn.f32x2 %0, %1, %2, %3;" : "=l"(r) : "l"(a), "l"(b), "l"(c)); return r;
}
__device__ __forceinline__ ull add2(ull a, ull b) {
    ull r; asm("add.rn.f32x2 %0, %1, %2;" : "=l"(r) : "l"(a), "l"(b)); return r;
}

// ---------------------------------------------------------------------------
// k_u: u[c,b,r,o] = sum_i x[b,r,i]*W[c,r,i,o] -> fp16. Pure compute (R5).
// Block (0,0) also resets the last-CTA counters for this run.
// ---------------------------------------------------------------------------
__global__ __launch_bounds__(128) void k_u(const float* __restrict__ x,
                                           const float* __restrict__ W)
{
    const int rt  = blockIdx.x, c = blockIdx.y;
    const int tid = threadIdx.x;
    if (rt == 0 && c == 0 && tid < 3) g_ctr[tid] = 0;

    const int o2  = tid & 7;
    const int rl  = tid >> 3;
    const int r   = rt * RT + rl;

    float w0[8], w1[8];
    {
        const float* Wp = W + (((size_t)c*Rr + r)*CI)*Oo + 2*o2;
        #pragma unroll
        for (int i = 0; i < 8; i++) {
            float2 v = *(const float2*)(Wp + i*Oo);
            w0[i] = v.x; w1[i] = v.y;
        }
    }

    const float4* xp = (const float4*)x;
    const size_t  xstep = (size_t)Rr*CI/4;
    const size_t  xbase = (size_t)r*CI/4;

    half2* udst = (half2*)g_uh + ((size_t)c*Bb*Rr + r)*8 + o2;

    float4 xa = xp[xbase], xb = xp[xbase+1];
    for (int b = 0; b < Bb; b++) {
        float4 na, nb;
        if (b + 1 < Bb) {
            size_t nx = xbase + (size_t)(b+1)*xstep;
            na = xp[nx]; nb = xp[nx+1];
        }
        float u0, u1;
        u0 =           xa.x*w0[0];        u1 =           xa.x*w1[0];
        u0 = fmaf(xa.y, w0[1], u0);       u1 = fmaf(xa.y, w1[1], u1);
        u0 = fmaf(xa.z, w0[2], u0);       u1 = fmaf(xa.z, w1[2], u1);
        u0 = fmaf(xa.w, w0[3], u0);       u1 = fmaf(xa.w, w1[3], u1);
        u0 = fmaf(xb.x, w0[4], u0);       u1 = fmaf(xb.x, w1[4], u1);
        u0 = fmaf(xb.y, w0[5], u0);       u1 = fmaf(xb.y, w1[5], u1);
        u0 = fmaf(xb.z, w0[6], u0);       u1 = fmaf(xb.z, w1[6], u1);
        u0 = fmaf(xb.w, w0[7], u0);       u1 = fmaf(xb.w, w1[7], u1);
        udst[(size_t)b*Rr*8] = __floats2half2_rn(u0, u1);
        xa = na; xb = nb;
    }
}

// ---------------------------------------------------------------------------
// k_s0: s1[cb,o] = mean_r u -> g_S; per-CTA sum s1^2 -> g_n2a; last CTA
// collapses the 640 partials to the scalar g_n2s[0].
// grid (64,10), 256 thr, 2 cb per CTA (R5-proven core).
// ---------------------------------------------------------------------------
__global__ __launch_bounds__(256) void k_s0()
{
    const int bx = blockIdx.x, c = blockIdx.y;
    const int tid = threadIdx.x;
    __shared__ float ss[8*256];
    __shared__ float pA[256];
    __shared__ float shn[256];
    __shared__ int   lastf;

    float qacc = 0.f;
    for (int bb = 0; bb < 2; bb++) {
        const int cb = c*Bb + bx*2 + bb;
        const float4* up = (const float4*)(g_uh + (size_t)cb*Rr*Oo);

        float s[8];
        #pragma unroll
        for (int j = 0; j < 8; j++) s[j] = 0.f;
        #pragma unroll
        for (int k = 0; k < 9; k++) {
            float4 raw = up[tid + k*256];
            const half2* hp = (const half2*)&raw;
            #pragma unroll
            for (int j = 0; j < 4; j++) {
                float2 f2 = __half22float2(hp[j]);
                s[2*j]   += f2.x;
                s[2*j+1] += f2.y;
            }
        }
        const int row = (tid >> 1) + (tid & 1)*128;
        #pragma unroll
        for (int j = 0; j < 8; j++) ss[j*256 + row] = s[j];
        __syncthreads();
        {
            const int h = tid >> 7, col = (tid >> 4) & 7, grp = tid & 15;
            float a = 0.f;
            #pragma unroll
            for (int i = 0; i < 8; i++) a += ss[col*256 + h*128 + grp + 16*i];
            pA[tid] = a;
        }
        __syncthreads();
        if (tid < 16) {
            const int h = tid >> 3, col = tid & 7;
            float st = 0.f;
            #pragma unroll
            for (int g2 = 0; g2 < 16; g2++) st += pA[h*128 + col*16 + g2];
            const float sn = st * (1.0f / (float)Rr);
            g_S[cb*16 + tid] = sn;
            qacc += sn * sn;
        }
        __syncthreads();
    }
    shn[tid] = qacc;
    __syncthreads();
    if (tid == 0) {
        float t = 0.f;
        #pragma unroll
        for (int i = 0; i < 16; i++) t += shn[i];
        g_n2a[c*gridDim.x + bx] = t;
    }

    // last-CTA tail: collapse 640 partials -> scalar
    __threadfence();
    __syncthreads();
    if (tid == 0) {
        int old = atomicAdd(&g_ctr[0], 1);
        lastf = (old == 640 - 1);
    }
    __syncthreads();
    if (lastf) {
        float a = g_n2a[tid] + g_n2a[tid + 256];
        if (tid < 128) a += g_n2a[tid + 512];
        shn[tid] = a;
        __syncthreads();
        for (int st = 128; st > 0; st >>= 1) {
            if (tid < st) shn[tid] += shn[tid + st];
            __syncthreads();
        }
        if (tid == 0) g_n2s[0] = shn[0];
    }
}

// ---------------------------------------------------------------------------
// k_it: SPLIT — each CTA handles one r-HALF of one cb. Whole half-tile
// prefetched in the prologue (DEPTH=9, no refills), barrier-free mainloop.
// Epilogue -> per-half z,s partials. Last CTA combines all halves:
//   sn = s/z -> g_S, n2 -> g_n2s[1] (iter2)  or  out = f3*sn (iter3).
// grid (256, 10) = 2560 CTAs x 128 thr.
// ---------------------------------------------------------------------------
__global__ __launch_bounds__(128) void k_it(int iter3, float* __restrict__ outp)
{
    __shared__ __align__(16) char ring[DEPTH*CHB];   // 18 KB
    __shared__ float shn[128];
    __shared__ int   lastf;

    const int tid  = threadIdx.x;
    const int cb   = blockIdx.y*Bb + (blockIdx.x >> 1);
    const int half = blockIdx.x & 1;
    const int p    = (tid & 1) * 8;
    const char* src = (const char*)(g_uh + (size_t)cb*Rr*Oo) + half*(NCHUNK*CHB);
    const int toff = tid*16;

    // prologue: prefetch the whole half-tile (9 chunks, 9 commit groups)
    #pragma unroll
    for (int k = 0; k < NCHUNK; k++) {
        __pipeline_memcpy_async(ring + k*CHB + toff, src + k*CHB + toff, 16);
        __pipeline_commit();
    }

    // scalar n2 -> K, V
    const float n2 = g_n2s[iter3 ? 1 : 0];
    const float K  = (sqrtf(n2) / (1.0f + n2)) * 1.4426950408889634f;

    ull V2[4];
    #pragma unroll
    for (int j = 0; j < 4; j++) {
        const int i0 = cb*16 + p + 2*j;
        float v0 = K * g_S[i0],   v1 = K * g_S[i0+1];
        if (iter3) { v0 += g_V[i0]; v1 += g_V[i0+1]; }
        V2[j] = pk2(v0, v1);
    }
    if (!iter3 && half == 0 && tid < 16) g_V[cb*16 + tid] = K * g_S[cb*16 + tid];

    const ull MAGIC2  = pk2(12582912.0f, 12582912.0f);
    const ull NMAGIC2 = pk2(-12582912.0f, -12582912.0f);
    const ull CF4 = pk2(0.0096181298f, 0.0096181298f);
    const ull CF3 = pk2(0.0555041087f, 0.0555041087f);
    const ull CF2 = pk2(0.2402265070f, 0.2402265070f);
    const ull CF1 = pk2(0.6931471806f, 0.6931471806f);
    const ull CF0 = pk2(1.0f, 1.0f);
    const ull SIGN64 = 0x8000000080000000ULL;

    ull z2[4], s2[4];
    #pragma unroll
    for (int j = 0; j < 4; j++) { z2[j] = 0ULL; s2[j] = 0ULL; }

    // barrier-free mainloop: wait_group 8 + empty commit per chunk keeps
    // the per-thread group accounting aligned (group k done before chunk k).
    #pragma unroll
    for (int k = 0; k < NCHUNK; k++) {
        asm volatile("cp.async.wait_group 8;" ::: "memory");
        float4 cur = *(const float4*)(ring + k*CHB + toff);
        __pipeline_commit();
        const half2* hp = (const half2*)&cur;
        #pragma unroll
        for (int j = 0; j < 4; j++) {
            float2 fu = __half22float2(hp[j]);
            ull u2 = pk2(fu.x, fu.y);
            ull t2 = fma2(u2, V2[j], MAGIC2);
            ull g2 = add2(t2, NMAGIC2);
            ull f2 = fma2(u2, V2[j], g2 ^ SIGN64);
            ull p2 = fma2(CF4, f2, CF3);
            p2 = fma2(p2, f2, CF2);
            p2 = fma2(p2, f2, CF1);
            p2 = fma2(p2, f2, CF0);
            float tlo, thi, plo, phi;
            upk2(t2, tlo, thi);
            upk2(p2, plo, phi);
            float e0 = __int_as_float(__float_as_int(plo) + (__float_as_int(tlo) << 23));
            float e1 = __int_as_float(__float_as_int(phi) + (__float_as_int(thi) << 23));
            ull e2 = pk2(e0, e1);
            z2[j] = add2(z2[j], e2);
            s2[j] = fma2(e2, u2, s2[j]);
        }
    }

    float z[8], s[8];
    #pragma unroll
    for (int j = 0; j < 4; j++) {
        upk2(z2[j], z[2*j], z[2*j+1]);
        upk2(s2[j], s[2*j], s[2*j+1]);
    }

    // epilogue reductions alias into the drained ring -> per-half partials
    __syncthreads();
    float* zs  = (float*)ring;           // 8*132 = 4224 B
    float* ssm = zs  + 8*132;            // 4224 B
    float* pAz = ssm + 8*132;            // 512 B
    float* pAs = pAz + 128;              // 512 B

    const int row = (tid >> 1) + (tid & 1)*64;
    #pragma unroll
    for (int j = 0; j < 8; j++) { zs[j*132 + row] = z[j]; ssm[j*132 + row] = s[j]; }
    __syncthreads();
    {
        const int h = tid >> 6, col = (tid >> 3) & 7, grp = tid & 7;
        float az = 0.f, as = 0.f;
        #pragma unroll
        for (int i = 0; i < 8; i++) {
            const int a = col*132 + h*64 + grp + 8*i;
            az += zs[a]; as += ssm[a];
        }
        pAz[tid] = az; pAs[tid] = as;
    }
    __syncthreads();
    if (tid < 16) {
        const int h = tid >> 3, col = tid & 7;
        float zt = 0.f, st = 0.f;
        #pragma unroll
        for (int g = 0; g < 8; g++) {
            const int a = h*64 + col*8 + g;
            zt += pAz[a]; st += pAs[a];
        }
        g_zp[cb*32 + half*16 + tid] = zt;
        g_sp[cb*32 + half*16 + tid] = st;
    }

    // ---- last-CTA tail: combine halves, n2 / final output ----
    __threadfence();
    __syncthreads();
    if (tid == 0) {
        int old = atomicAdd(&g_ctr[iter3 ? 2 : 1], 1);
        lastf = (old == NIT_CTAS - 1);
    }
    __syncthreads();
    if (!lastf) return;

    float q = 0.f;
    for (int i = tid; i < NS; i += 128) {
        const int base = (i >> 4)*32 + (i & 15);
        const float zv = g_zp[base] + g_zp[base + 16];
        const float sv = g_sp[base] + g_sp[base + 16];
        const float sn = sv / zv;
        g_S[i] = sn;
        q += sn * sn;
    }
    shn[tid] = q;
    __syncthreads();
    for (int st = 64; st > 0; st >>= 1) {
        if (tid < st) shn[tid] += shn[tid + st];
        __syncthreads();
    }
    const float n2n = shn[0];
    if (!iter3) {
        if (tid == 0) g_n2s[1] = n2n;
    } else {
        const float f3 = sqrtf(n2n) / (1.0f + n2n);
        for (int i = tid; i < NS; i += 128)
            outp[i] = f3 * g_S[i];
    }
}

// ---------------------------------------------------------------------------
extern "C" void kernel_launch(void* const* d_in, const int* in_sizes, int n_in,
                              void* d_out, int out_size)
{
    const float* x = (const float*)d_in[0];   // [128,1152,8]
    const float* W = (const float*)d_in[1];   // [10,1152,8,16]
    float* out = (float*)d_out;               // 20480 floats
    (void)in_sizes; (void)n_in; (void)out_size;

    k_u  <<<dim3(NRT, Cc), 128>>>(x, W);
    k_s0 <<<dim3(Bb/2, Cc), 256>>>();            // iter 1 + scalar n2
    k_it <<<dim3(Bb*2, Cc), 128>>>(0, nullptr);  // iter 2 + tail combine
    k_it <<<dim3(Bb*2, Cc), 128>>>(1, out);      // iter 3 + tail squash -> out
}